// round 5
// baseline (speedup 1.0000x reference)
#include <cuda_runtime.h>
#include <cstdint>
#include <cstddef>

#define BB 64
#define TT 512
#define DD 128
#define HH 256
#define GG 1024   // 4*H
#define CC 50

// ---------------- device scratch (no allocations allowed) ------------------
static __device__ float    g_xg[(size_t)2 * BB * TT * GG];   // 256 MiB
static __device__ float    g_h [(size_t)2 * BB * TT * HH];   // 64 MiB
static __device__ float    g_hx[2 * 2 * BB * HH];            // parity x dir x b x h
static __device__ unsigned g_cnt;
static __device__ float    g_logits[(size_t)BB * TT * CC];
static __device__ float    g_loss[BB];

// ---------------- kernel: reset barrier + h exchange buffers ---------------
__global__ void k_init()
{
    int i = blockIdx.x * blockDim.x + threadIdx.x;   // 64*256 = 16384 threads
    #pragma unroll
    for (int q = 0; q < 4; q++)
        g_hx[i + q * 16384] = 0.f;
    if (i == 0) g_cnt = 0u;
}

// ---------------- kernel: xg = emb[words(_rev)] @ W_ih^T + b ---------------
// GEMM M=32768 (b,s), N=1024, K=128, per direction. Tile 64x64, K chunk 64.
__global__ __launch_bounds__(256) void k_xg(
    const int* __restrict__ words, const int* __restrict__ seq_len,
    const float* __restrict__ emb,
    const float* __restrict__ Wf, const float* __restrict__ bfv,
    const float* __restrict__ Wb, const float* __restrict__ bbv)
{
    __shared__ float As[64 * 64];   // [k][m]
    __shared__ float Bs[64 * 64];   // [k][n]
    const int tid = threadIdx.x;
    const int mt = blockIdx.x, nt = blockIdx.y, dir = blockIdx.z;
    const float* W    = dir ? Wb  : Wf;
    const float* bias = dir ? bbv : bfv;

    const int m  = tid >> 2;        // 0..63
    const int kq = tid & 3;         // 0..3 (16 k each)

    // row -> (batch, step) with reverse gather for backward direction
    int grow = mt * 64 + m;
    int b = grow >> 9, s = grow & 511;
    int tmap = s;
    if (dir) { int L = seq_len[b]; tmap = (s < L) ? (L - 1 - s) : s; }
    const float* xrow = emb + (size_t)words[b * TT + tmap] * DD;
    const float* wrow = W + (size_t)(nt * 64 + m) * DD;

    float acc[4][4];
    #pragma unroll
    for (int i = 0; i < 4; i++)
        #pragma unroll
        for (int j = 0; j < 4; j++) acc[i][j] = 0.f;

    const int m0 = (tid >> 4) << 2;
    const int n0 = (tid & 15) << 2;

    for (int kc = 0; kc < 128; kc += 64) {
        __syncthreads();
        #pragma unroll
        for (int i = 0; i < 4; i++) {
            int k = kq * 16 + i * 4;
            float4 v = *(const float4*)(xrow + kc + k);
            As[(k + 0) * 64 + m] = v.x; As[(k + 1) * 64 + m] = v.y;
            As[(k + 2) * 64 + m] = v.z; As[(k + 3) * 64 + m] = v.w;
            float4 u = *(const float4*)(wrow + kc + k);
            Bs[(k + 0) * 64 + m] = u.x; Bs[(k + 1) * 64 + m] = u.y;
            Bs[(k + 2) * 64 + m] = u.z; Bs[(k + 3) * 64 + m] = u.w;
        }
        __syncthreads();
        #pragma unroll 8
        for (int k = 0; k < 64; k++) {
            float4 a4 = *(const float4*)(As + k * 64 + m0);
            float4 b4 = *(const float4*)(Bs + k * 64 + n0);
            float av[4] = {a4.x, a4.y, a4.z, a4.w};
            float bv[4] = {b4.x, b4.y, b4.z, b4.w};
            #pragma unroll
            for (int i = 0; i < 4; i++)
                #pragma unroll
                for (int j = 0; j < 4; j++)
                    acc[i][j] += av[i] * bv[j];
        }
    }

    #pragma unroll
    for (int i = 0; i < 4; i++) {
        int row = mt * 64 + m0 + i;
        int b2 = row >> 9, s2 = row & 511;
        size_t base = (((size_t)(dir * BB + b2)) * TT + s2) * (size_t)GG + nt * 64 + n0;
        float4 o;
        o.x = acc[i][0] + __ldg(&bias[nt * 64 + n0 + 0]);
        o.y = acc[i][1] + __ldg(&bias[nt * 64 + n0 + 1]);
        o.z = acc[i][2] + __ldg(&bias[nt * 64 + n0 + 2]);
        o.w = acc[i][3] + __ldg(&bias[nt * 64 + n0 + 3]);
        *(float4*)&g_xg[base] = o;
    }
}

// ---------------- kernel: persistent LSTM recurrence (both dirs) -----------
// 128 CTAs: dir(2) x batch-group(8, 8 batches) x h-group(8, 32 h).
// W_hh slice transposed in smem (128 KB). One global spin barrier per step.
__global__ __launch_bounds__(256, 1) void k_lstm(
    const int* __restrict__ seq_len,
    const float* __restrict__ Whhf, const float* __restrict__ Whhb)
{
    extern __shared__ float sm[];
    float* Wt  = sm;            // [k=256][r=128] transposed weights: 32768 f
    float* hs  = sm + 32768;    // [b=8][k=256]                      : 2048 f
    float* red = sm + 34816;    // [w=8][g=4][b=8][j=32]             : 8192 f

    const int bx  = blockIdx.x;
    const int dir = bx >> 6, bg = (bx >> 3) & 7, jg = bx & 7;
    const int tid = threadIdx.x;
    const int w   = tid >> 5, j = tid & 31;     // compute role: k-slice warp, h lane
    const int rb  = tid >> 5, rj = tid & 31;    // reduce role: batch, h lane
    const float* Whh = dir ? Whhb : Whhf;

    // load transposed weight slice: rows r = gate*32 + lane -> grow
    {
        int r = tid >> 1, half = tid & 1;
        int gr = (r >> 5) * HH + jg * 32 + (r & 31);
        const float4* src = (const float4*)(Whh + (size_t)gr * HH + half * 128);
        #pragma unroll 8
        for (int i = 0; i < 32; i++) {
            float4 v = src[i];
            int k = half * 128 + i * 4;
            Wt[(k + 0) * 128 + r] = v.x; Wt[(k + 1) * 128 + r] = v.y;
            Wt[(k + 2) * 128 + r] = v.z; Wt[(k + 3) * 128 + r] = v.w;
        }
    }
    const int bglob = bg * 8 + rb;
    const int jglob = jg * 32 + rj;
    const int L = seq_len[bglob];
    float cst = 0.f;
    __syncthreads();

    for (int s = 0; s < TT; s++) {
        const int rp = s & 1, wp = rp ^ 1;
        // load previous h for our 8 batches (L2-coherent reads)
        {
            const float4* src = (const float4*)(g_hx + ((size_t)(rp * 2 + dir) * BB + bg * 8) * HH);
            float4* dst = (float4*)hs;
            dst[tid]       = __ldcg(src + tid);
            dst[tid + 256] = __ldcg(src + tid + 256);
        }
        __syncthreads();

        // partial matvec: warp w covers k in [w*32, w*32+32)
        float acc[4][8];
        #pragma unroll
        for (int g = 0; g < 4; g++)
            #pragma unroll
            for (int bb = 0; bb < 8; bb++) acc[g][bb] = 0.f;

        const float* wk = Wt + (w * 32) * 128;
        const int kofs = w * 32;
        #pragma unroll 4
        for (int kk = 0; kk < 32; kk++) {
            float hv[8];
            #pragma unroll
            for (int bb = 0; bb < 8; bb++) hv[bb] = hs[bb * 256 + kofs + kk];
            #pragma unroll
            for (int g = 0; g < 4; g++) {
                float wt = wk[kk * 128 + g * 32 + j];
                #pragma unroll
                for (int bb = 0; bb < 8; bb++) acc[g][bb] += wt * hv[bb];
            }
        }
        #pragma unroll
        for (int g = 0; g < 4; g++)
            #pragma unroll
            for (int bb = 0; bb < 8; bb++)
                red[((w * 4 + g) * 8 + bb) * 32 + j] = acc[g][bb];
        __syncthreads();

        // reduce across warps + gate nonlinearity; thread = (rb, rj)
        float gs[4];
        #pragma unroll
        for (int g = 0; g < 4; g++) {
            float v = 0.f;
            #pragma unroll
            for (int ww = 0; ww < 8; ww++)
                v += red[((ww * 4 + g) * 8 + rb) * 32 + rj];
            gs[g] = v;
        }
        size_t xga = (((size_t)(dir * BB + bglob)) * TT + s) * (size_t)GG + jg * 32 + rj;
        float xi = __ldg(&g_xg[xga]);
        float xf = __ldg(&g_xg[xga + 256]);
        float xg = __ldg(&g_xg[xga + 512]);
        float xo = __ldg(&g_xg[xga + 768]);
        float iv = 1.f / (1.f + expf(-(xi + gs[0])));
        float fv = 1.f / (1.f + expf(-(xf + gs[1])));
        float gv = tanhf(xg + gs[2]);
        float ov = 1.f / (1.f + expf(-(xo + gs[3])));
        cst = fv * cst + iv * gv;
        float hv = ov * tanhf(cst);

        g_hx[((size_t)(wp * 2 + dir) * BB + bglob) * HH + jglob] = hv;
        int pos = dir ? ((s < L) ? (L - 1 - s) : s) : s;
        g_h[(((size_t)dir * BB + bglob) * TT + pos) * HH + jglob] = hv;

        // chip-wide barrier (monotonic counter; all 128 CTAs resident)
        __threadfence();
        __syncthreads();
        if (tid == 0) {
            atomicAdd(&g_cnt, 1u);
            unsigned target = (unsigned)(s + 1) * 128u;
            while (*((volatile unsigned*)&g_cnt) < target) {}
        }
        __syncthreads();
    }
}

// ---------------- kernel: feats = hcat @ fc_W^T + fc_b, log_softmax --------
__global__ __launch_bounds__(256, 1) void k_feats(
    const float* __restrict__ fcW, const float* __restrict__ fcb)
{
    extern __shared__ float sm[];
    float* Ws   = sm;            // 25600 floats (fc_W)
    float* hrow = sm + 25600;    // 512
    float* slog = sm + 26112;    // 64
    float* slse = sm + 26176;    // 16 pad
    const int tid = threadIdx.x;

    for (int i = tid; i < 6400; i += 256)
        ((float4*)Ws)[i] = ((const float4*)fcW)[i];
    __syncthreads();

    const int row0 = blockIdx.x * 32;
    const int cc = min(tid >> 2, CC - 1);
    const int kq = tid & 3;

    for (int rr = 0; rr < 32; rr++) {
        int row = row0 + rr;
        int b = row >> 9, t = row & 511;
        const float* hf = g_h + (((size_t)0 * BB + b) * TT + t) * HH;
        const float* hb = g_h + (((size_t)1 * BB + b) * TT + t) * HH;
        hrow[tid]       = hf[tid];
        hrow[256 + tid] = hb[tid];
        __syncthreads();

        float acc = 0.f;
        const float4* wp = (const float4*)(Ws + cc * 512 + kq * 128);
        const float4* hp = (const float4*)(hrow + kq * 128);
        #pragma unroll 8
        for (int i = 0; i < 32; i++) {
            float4 a = wp[i], h = hp[i];
            acc += a.x * h.x + a.y * h.y + a.z * h.z + a.w * h.w;
        }
        acc += __shfl_xor_sync(0xFFFFFFFFu, acc, 1);
        acc += __shfl_xor_sync(0xFFFFFFFFu, acc, 2);
        if (kq == 0 && tid < CC * 4) slog[cc] = acc + __ldg(&fcb[cc]);
        __syncthreads();

        if (tid < 32) {
            float v0 = slog[tid];
            float v1 = (tid + 32 < CC) ? slog[tid + 32] : -1e30f;
            float mx = fmaxf(v0, v1);
            #pragma unroll
            for (int o = 16; o; o >>= 1) mx = fmaxf(mx, __shfl_xor_sync(0xFFFFFFFFu, mx, o));
            float sum = expf(v0 - mx) + ((tid + 32 < CC) ? expf(v1 - mx) : 0.f);
            #pragma unroll
            for (int o = 16; o; o >>= 1) sum += __shfl_xor_sync(0xFFFFFFFFu, sum, o);
            if (tid == 0) slse[0] = mx + logf(sum);
        }
        __syncthreads();
        if (tid < CC) g_logits[(size_t)row * CC + tid] = slog[tid] - slse[0];
        __syncthreads();
    }
}

// ---------------- kernel: CRF forward + gold score per batch ---------------
__global__ void k_crf(const int* __restrict__ target, const int* __restrict__ seq_len,
                      const float* __restrict__ trans,
                      const float* __restrict__ start_s, const float* __restrict__ end_s)
{
    __shared__ float tr[CC * CC];
    __shared__ float alpha[64];
    __shared__ float redsm[64];
    __shared__ float shn[1];
    const int b = blockIdx.x, tid = threadIdx.x;

    for (int i = tid; i < CC * CC; i += 64) tr[i] = trans[i];
    const int L = seq_len[b];
    const float* lg = g_logits + (size_t)b * TT * CC;
    if (tid < CC) alpha[tid] = lg[tid] + start_s[tid];
    __syncthreads();

    for (int t = 1; t < L; t++) {
        float nv = 0.f;
        if (tid < CC) {
            float mx = -1e30f;
            #pragma unroll 10
            for (int i = 0; i < CC; i++)
                mx = fmaxf(mx, alpha[i] + tr[i * CC + tid]);
            float s = 0.f;
            #pragma unroll 10
            for (int i = 0; i < CC; i++)
                s += expf(alpha[i] + tr[i * CC + tid] - mx);
            nv = mx + logf(s) + lg[(size_t)t * CC + tid];
        }
        __syncthreads();
        if (tid < CC) alpha[tid] = nv;
        __syncthreads();
    }

    if (tid < 32) {
        float v0 = alpha[tid] + end_s[tid];
        float v1 = (tid + 32 < CC) ? (alpha[tid + 32] + end_s[tid + 32]) : -1e30f;
        float mx = fmaxf(v0, v1);
        #pragma unroll
        for (int o = 16; o; o >>= 1) mx = fmaxf(mx, __shfl_xor_sync(0xFFFFFFFFu, mx, o));
        float s = expf(v0 - mx) + ((tid + 32 < CC) ? expf(v1 - mx) : 0.f);
        #pragma unroll
        for (int o = 16; o; o >>= 1) s += __shfl_xor_sync(0xFFFFFFFFu, s, o);
        if (tid == 0) shn[0] = mx + logf(s);
    }

    const int* tg = target + b * TT;
    float part = 0.f;
    for (int t = tid; t < L; t += 64) {
        int c = tg[t];
        part += lg[(size_t)t * CC + c];
        if (t >= 1) part += tr[tg[t - 1] * CC + c];
    }
    redsm[tid] = part;
    __syncthreads();
    if (tid < 32) {
        float v = redsm[tid] + redsm[tid + 32];
        #pragma unroll
        for (int o = 16; o; o >>= 1) v += __shfl_xor_sync(0xFFFFFFFFu, v, o);
        if (tid == 0) {
            float gold = v + start_s[tg[0]] + end_s[tg[L - 1]];
            g_loss[b] = shn[0] - gold;
        }
    }
}

// ---------------- kernel: final mean ---------------------------------------
__global__ void k_final(float* __restrict__ out)
{
    __shared__ float s[64];
    int tid = threadIdx.x;
    s[tid] = g_loss[tid];
    __syncthreads();
    if (tid < 32) {
        float v = s[tid] + s[tid + 32];
        #pragma unroll
        for (int o = 16; o; o >>= 1) v += __shfl_xor_sync(0xFFFFFFFFu, v, o);
        if (tid == 0) out[0] = v / 64.f;
    }
}

// ---------------------------------------------------------------------------
extern "C" void kernel_launch(void* const* d_in, const int* in_sizes, int n_in,
                              void* d_out, int out_size)
{
    const int*   words  = (const int*)  d_in[0];
    const int*   target = (const int*)  d_in[1];
    const int*   seqlen = (const int*)  d_in[2];
    const float* emb    = (const float*)d_in[3];
    const float* Wihf   = (const float*)d_in[4];
    const float* Whhf   = (const float*)d_in[5];
    const float* bf     = (const float*)d_in[6];
    const float* Wihb   = (const float*)d_in[7];
    const float* Whhb   = (const float*)d_in[8];
    const float* bb     = (const float*)d_in[9];
    const float* fcW    = (const float*)d_in[10];
    const float* fcb    = (const float*)d_in[11];
    const float* trans  = (const float*)d_in[12];
    const float* starts = (const float*)d_in[13];
    const float* ends   = (const float*)d_in[14];
    float* out = (float*)d_out;

    cudaFuncSetAttribute(k_lstm,  cudaFuncAttributeMaxDynamicSharedMemorySize, 172032);
    cudaFuncSetAttribute(k_feats, cudaFuncAttributeMaxDynamicSharedMemorySize, 104768);

    k_init<<<64, 256>>>();
    dim3 gx(512, 16, 2);
    k_xg<<<gx, 256>>>(words, seqlen, emb, Wihf, bf, Wihb, bb);
    k_lstm<<<128, 256, 172032>>>(seqlen, Whhf, Whhb);
    k_feats<<<1024, 256, 104768>>>(fcW, fcb);
    k_crf<<<64, 64>>>(target, seqlen, trans, starts, ends);
    k_final<<<1, 64>>>(out);
}

// round 7
// speedup vs baseline: 1.0493x; 1.0493x over previous
#include <cuda_runtime.h>
#include <cstdint>
#include <cstddef>

#define BB 64
#define TT 512
#define DD 128
#define HH 256
#define GG 1024   // 4*H
#define CC 50

typedef unsigned long long ull;

// ---------------- packed f32x2 helpers -------------------------------------
__device__ __forceinline__ void fma2(ull& d, ull a, ull b)
{
    asm("fma.rn.f32x2 %0, %1, %2, %0;" : "+l"(d) : "l"(a), "l"(b));
}
__device__ __forceinline__ ull add2(ull a, ull b)
{
    ull r; asm("add.rn.f32x2 %0, %1, %2;" : "=l"(r) : "l"(a), "l"(b)); return r;
}
__device__ __forceinline__ ull pack2(float x, float y)
{
    ull r; asm("mov.b64 %0, {%1, %2};" : "=l"(r) : "f"(x), "f"(y)); return r;
}

// ---------------- device scratch (no allocations allowed) ------------------
static __device__ float    g_xg[(size_t)2 * BB * TT * GG];   // 256 MiB
static __device__ float    g_h [(size_t)2 * BB * TT * HH];   // 64 MiB
static __device__ float    g_hx[2 * 2 * BB * HH];            // parity x dir x bg x k x b
static __device__ unsigned g_cnt;
static __device__ float    g_logits[(size_t)BB * TT * CC];
static __device__ float    g_loss[BB];

// ---------------- kernel: reset barrier + h exchange buffers ---------------
__global__ void k_init()
{
    int i = blockIdx.x * blockDim.x + threadIdx.x;   // 64*256 = 16384 threads
    #pragma unroll
    for (int q = 0; q < 4; q++)
        g_hx[i + q * 16384] = 0.f;
    if (i == 0) g_cnt = 0u;
}

// ---------------- kernel: xg = emb[words(_rev)] @ W_ih^T + b ---------------
// GEMM M=32768 (b,s), N=1024, K=128, per direction. 128x128 block, 8x8 thread
// tile, full K=128 resident in smem, packed f32x2 FMA.
__global__ __launch_bounds__(256) void k_xg(
    const int* __restrict__ words, const int* __restrict__ seq_len,
    const float* __restrict__ emb,
    const float* __restrict__ Wf, const float* __restrict__ bfv,
    const float* __restrict__ Wb, const float* __restrict__ bbv)
{
    extern __shared__ float xs[];
    float* As = xs;           // [k=128][m=128] : 64 KB
    float* Bs = xs + 16384;   // [k=128][n=128] : 64 KB
    const int tid = threadIdx.x;
    const int mt = blockIdx.x, nt = blockIdx.y, dir = blockIdx.z;
    const float* W    = dir ? Wb  : Wf;
    const float* bias = dir ? bbv : bfv;

    // --- load tiles: thread (row=tid>>1, half=tid&1) loads 64 floats per mat
    {
        const int mrow = tid >> 1, half = tid & 1;
        int grow = mt * 128 + mrow;
        int b = grow >> 9, s = grow & 511;
        int tmap = s;
        if (dir) { int L = seq_len[b]; tmap = (s < L) ? (L - 1 - s) : s; }
        const float* xrow = emb + (size_t)words[b * TT + tmap] * DD + half * 64;
        const float* wrow = W + (size_t)(nt * 128 + mrow) * DD + half * 64;
        #pragma unroll
        for (int i = 0; i < 16; i++) {
            float4 v = ((const float4*)xrow)[i];
            int k = half * 64 + i * 4;
            As[(k + 0) * 128 + mrow] = v.x; As[(k + 1) * 128 + mrow] = v.y;
            As[(k + 2) * 128 + mrow] = v.z; As[(k + 3) * 128 + mrow] = v.w;
            float4 u = ((const float4*)wrow)[i];
            Bs[(k + 0) * 128 + mrow] = u.x; Bs[(k + 1) * 128 + mrow] = u.y;
            Bs[(k + 2) * 128 + mrow] = u.z; Bs[(k + 3) * 128 + mrow] = u.w;
        }
    }
    __syncthreads();

    const int m0 = (tid >> 4) << 3;
    const int n0 = (tid & 15) << 3;

    ull acc[8][4];
    #pragma unroll
    for (int i = 0; i < 8; i++)
        #pragma unroll
        for (int p = 0; p < 4; p++) acc[i][p] = 0ull;

    #pragma unroll 4
    for (int k = 0; k < 128; k++) {
        const float* ar = As + k * 128 + m0;
        const float* br = Bs + k * 128 + n0;
        float4 a0 = *(const float4*)ar;
        float4 a1 = *(const float4*)(ar + 4);
        ulonglong2 bA = *(const ulonglong2*)br;
        ulonglong2 bB = *(const ulonglong2*)(br + 4);
        ull b4[4] = { bA.x, bA.y, bB.x, bB.y };
        float am[8] = { a0.x, a0.y, a0.z, a0.w, a1.x, a1.y, a1.z, a1.w };
        #pragma unroll
        for (int i = 0; i < 8; i++) {
            ull ad = pack2(am[i], am[i]);
            #pragma unroll
            for (int p = 0; p < 4; p++) fma2(acc[i][p], ad, b4[p]);
        }
    }

    // --- epilogue: add bias (packed), store
    ulonglong2 bb0 = *(const ulonglong2*)(bias + nt * 128 + n0);
    ulonglong2 bb1 = *(const ulonglong2*)(bias + nt * 128 + n0 + 4);
    ull bv4[4] = { bb0.x, bb0.y, bb1.x, bb1.y };
    #pragma unroll
    for (int i = 0; i < 8; i++) {
        int row = mt * 128 + m0 + i;
        int b2 = row >> 9, s2 = row & 511;
        size_t base = (((size_t)(dir * BB + b2)) * TT + s2) * (size_t)GG + nt * 128 + n0;
        ull* out = (ull*)&g_xg[base];
        #pragma unroll
        for (int p = 0; p < 4; p++) out[p] = add2(acc[i][p], bv4[p]);
    }
}

// ---------------- kernel: persistent LSTM recurrence (both dirs) -----------
// 128 CTAs: dir(2) x batch-group(8, 8 batches) x h-group(8, 32 h).
// Wt smem [k=256][j*4+g] (128 KB), hs [k][b] (8 KB), red 4096 ull (32 KB).
// Packed f32x2 matvec. One global spin barrier per step.
__global__ __launch_bounds__(256, 1) void k_lstm(
    const int* __restrict__ seq_len,
    const float* __restrict__ Whhf, const float* __restrict__ Whhb)
{
    extern __shared__ float sm[];
    float* Wt   = sm;            // [k=256][r=128], r=j*4+g : 32768 f
    float* hs   = sm + 32768;    // [k=256][b=8]            : 2048 f
    ull*   red2 = (ull*)(sm + 34816);  // [w][g][bp][j] = 4096 ull

    const int bx  = blockIdx.x;
    const int dir = bx >> 6, bg = (bx >> 3) & 7, jg = bx & 7;
    const int tid = threadIdx.x;
    const int w   = tid >> 5, j = tid & 31;     // compute: k-slice warp, h lane
    const int rb  = tid >> 5, rj = tid & 31;    // reduce: batch, h lane
    const float* Whh = dir ? Whhb : Whhf;

    // load weight slice: r = j*4+g  <-  global row g*256 + jg*32 + j
    {
        int r = tid >> 1, half = tid & 1;
        int jj = r >> 2, g = r & 3;
        const float4* src = (const float4*)(Whh + (size_t)(g * HH + jg * 32 + jj) * HH + half * 128);
        #pragma unroll 8
        for (int i = 0; i < 32; i++) {
            float4 v = src[i];
            int k = half * 128 + i * 4;
            Wt[(k + 0) * 128 + r] = v.x; Wt[(k + 1) * 128 + r] = v.y;
            Wt[(k + 2) * 128 + r] = v.z; Wt[(k + 3) * 128 + r] = v.w;
        }
    }
    const int bglob = bg * 8 + rb;
    const int L = seq_len[bglob];
    float cst = 0.f;
    __syncthreads();

    for (int s = 0; s < TT; s++) {
        const int rp = s & 1, wp = rp ^ 1;
        // load previous h block [k=256][b=8] (contiguous 8KB, L2-coherent)
        {
            const float4* src = (const float4*)(g_hx + ((size_t)((rp * 2 + dir) * 8 + bg)) * 2048);
            float4* dst = (float4*)hs;
            dst[tid]       = __ldcg(src + tid);
            dst[tid + 256] = __ldcg(src + tid + 256);
        }
        __syncthreads();

        // partial matvec: warp w covers k in [w*32, w*32+32)
        ull acc[4][4];   // [gate][batch-pair]
        #pragma unroll
        for (int g = 0; g < 4; g++)
            #pragma unroll
            for (int p = 0; p < 4; p++) acc[g][p] = 0ull;

        const float* wrow = Wt + (w * 32) * 128 + j * 4;
        const float* hrow = hs + (w * 32) * 8;
        #pragma unroll 8
        for (int kk = 0; kk < 32; kk++) {
            float4 wt = *(const float4*)(wrow + kk * 128);
            ulonglong2 ha = *(const ulonglong2*)(hrow + kk * 8);
            ulonglong2 hb = *(const ulonglong2*)(hrow + kk * 8 + 4);
            ull h4[4] = { ha.x, ha.y, hb.x, hb.y };
            ull wd[4] = { pack2(wt.x, wt.x), pack2(wt.y, wt.y),
                          pack2(wt.z, wt.z), pack2(wt.w, wt.w) };
            #pragma unroll
            for (int g = 0; g < 4; g++)
                #pragma unroll
                for (int p = 0; p < 4; p++) fma2(acc[g][p], wd[g], h4[p]);
        }
        #pragma unroll
        for (int g = 0; g < 4; g++)
            #pragma unroll
            for (int p = 0; p < 4; p++)
                red2[((w * 4 + g) * 4 + p) * 32 + j] = acc[g][p];

        // prefetch xg gates while reduce data drains
        size_t xga = (((size_t)(dir * BB + bglob)) * TT + s) * (size_t)GG + jg * 32 + rj;
        float xi = __ldg(&g_xg[xga]);
        float xf = __ldg(&g_xg[xga + 256]);
        float xg = __ldg(&g_xg[xga + 512]);
        float xo = __ldg(&g_xg[xga + 768]);
        __syncthreads();

        // reduce across 8 warps; thread = (batch rb, h lane rj)
        const float* redf = (const float*)red2;
        const int bp = rb >> 1, half = rb & 1;
        float gs[4];
        #pragma unroll
        for (int g = 0; g < 4; g++) {
            float v = 0.f;
            #pragma unroll
            for (int ww = 0; ww < 8; ww++)
                v += redf[(((ww * 4 + g) * 4 + bp) * 32 + rj) * 2 + half];
            gs[g] = v;
        }
        float iv = 1.f / (1.f + expf(-(xi + gs[0])));
        float fv = 1.f / (1.f + expf(-(xf + gs[1])));
        float gv = tanhf(xg + gs[2]);
        float ov = 1.f / (1.f + expf(-(xo + gs[3])));
        cst = fv * cst + iv * gv;
        float hv = ov * tanhf(cst);

        // write h: exchange buffer [parity][dir][bg][k][b] + output tensor
        g_hx[((size_t)((wp * 2 + dir) * 8 + bg)) * 2048 + (size_t)(jg * 32 + rj) * 8 + rb] = hv;
        int pos = dir ? ((s < L) ? (L - 1 - s) : s) : s;
        g_h[(((size_t)dir * BB + bglob) * TT + pos) * HH + jg * 32 + rj] = hv;

        // chip-wide barrier (monotonic counter; all 128 CTAs resident)
        __threadfence();
        __syncthreads();
        if (tid == 0) {
            atomicAdd(&g_cnt, 1u);
            unsigned target = (unsigned)(s + 1) * 128u;
            while (*((volatile unsigned*)&g_cnt) < target) {}
        }
        __syncthreads();
    }
}

// ---------------- kernel: feats = hcat @ fc_W^T + fc_b, log_softmax --------
__global__ __launch_bounds__(256, 1) void k_feats(
    const float* __restrict__ fcW, const float* __restrict__ fcb)
{
    extern __shared__ float sm[];
    float* Ws   = sm;            // 25600 floats (fc_W)
    float* hrow = sm + 25600;    // 512
    float* slog = sm + 26112;    // 64
    float* slse = sm + 26176;    // 16 pad
    const int tid = threadIdx.x;

    for (int i = tid; i < 6400; i += 256)
        ((float4*)Ws)[i] = ((const float4*)fcW)[i];
    __syncthreads();

    const int row0 = blockIdx.x * 32;
    const int cc = min(tid >> 2, CC - 1);
    const int kq = tid & 3;

    for (int rr = 0; rr < 32; rr++) {
        int row = row0 + rr;
        int b = row >> 9, t = row & 511;
        const float* hf = g_h + (((size_t)0 * BB + b) * TT + t) * HH;
        const float* hb = g_h + (((size_t)1 * BB + b) * TT + t) * HH;
        hrow[tid]       = hf[tid];
        hrow[256 + tid] = hb[tid];
        __syncthreads();

        float acc = 0.f;
        const float4* wp = (const float4*)(Ws + cc * 512 + kq * 128);
        const float4* hp = (const float4*)(hrow + kq * 128);
        #pragma unroll 8
        for (int i = 0; i < 32; i++) {
            float4 a = wp[i], h = hp[i];
            acc += a.x * h.x + a.y * h.y + a.z * h.z + a.w * h.w;
        }
        acc += __shfl_xor_sync(0xFFFFFFFFu, acc, 1);
        acc += __shfl_xor_sync(0xFFFFFFFFu, acc, 2);
        if (kq == 0 && tid < CC * 4) slog[cc] = acc + __ldg(&fcb[cc]);
        __syncthreads();

        if (tid < 32) {
            float v0 = slog[tid];
            float v1 = (tid + 32 < CC) ? slog[tid + 32] : -1e30f;
            float mx = fmaxf(v0, v1);
            #pragma unroll
            for (int o = 16; o; o >>= 1) mx = fmaxf(mx, __shfl_xor_sync(0xFFFFFFFFu, mx, o));
            float sum = expf(v0 - mx) + ((tid + 32 < CC) ? expf(v1 - mx) : 0.f);
            #pragma unroll
            for (int o = 16; o; o >>= 1) sum += __shfl_xor_sync(0xFFFFFFFFu, sum, o);
            if (tid == 0) slse[0] = mx + logf(sum);
        }
        __syncthreads();
        if (tid < CC) g_logits[(size_t)row * CC + tid] = slog[tid] - slse[0];
        __syncthreads();
    }
}

// ---------------- kernel: CRF forward + gold score per batch ---------------
__global__ void k_crf(const int* __restrict__ target, const int* __restrict__ seq_len,
                      const float* __restrict__ trans,
                      const float* __restrict__ start_s, const float* __restrict__ end_s)
{
    __shared__ float tr[CC * CC];
    __shared__ float alpha[64];
    __shared__ float redsm[64];
    __shared__ float shn[1];
    const int b = blockIdx.x, tid = threadIdx.x;

    for (int i = tid; i < CC * CC; i += 64) tr[i] = trans[i];
    const int L = seq_len[b];
    const float* lg = g_logits + (size_t)b * TT * CC;
    if (tid < CC) alpha[tid] = lg[tid] + start_s[tid];
    __syncthreads();

    for (int t = 1; t < L; t++) {
        float nv = 0.f;
        if (tid < CC) {
            float mx = -1e30f;
            #pragma unroll 10
            for (int i = 0; i < CC; i++)
                mx = fmaxf(mx, alpha[i] + tr[i * CC + tid]);
            float s = 0.f;
            #pragma unroll 10
            for (int i = 0; i < CC; i++)
                s += expf(alpha[i] + tr[i * CC + tid] - mx);
            nv = mx + logf(s) + lg[(size_t)t * CC + tid];
        }
        __syncthreads();
        if (tid < CC) alpha[tid] = nv;
        __syncthreads();
    }

    if (tid < 32) {
        float v0 = alpha[tid] + end_s[tid];
        float v1 = (tid + 32 < CC) ? (alpha[tid + 32] + end_s[tid + 32]) : -1e30f;
        float mx = fmaxf(v0, v1);
        #pragma unroll
        for (int o = 16; o; o >>= 1) mx = fmaxf(mx, __shfl_xor_sync(0xFFFFFFFFu, mx, o));
        float s = expf(v0 - mx) + ((tid + 32 < CC) ? expf(v1 - mx) : 0.f);
        #pragma unroll
        for (int o = 16; o; o >>= 1) s += __shfl_xor_sync(0xFFFFFFFFu, s, o);
        if (tid == 0) shn[0] = mx + logf(s);
    }

    const int* tg = target + b * TT;
    float part = 0.f;
    for (int t = tid; t < L; t += 64) {
        int c = tg[t];
        part += lg[(size_t)t * CC + c];
        if (t >= 1) part += tr[tg[t - 1] * CC + c];
    }
    redsm[tid] = part;
    __syncthreads();
    if (tid < 32) {
        float v = redsm[tid] + redsm[tid + 32];
        #pragma unroll
        for (int o = 16; o; o >>= 1) v += __shfl_xor_sync(0xFFFFFFFFu, v, o);
        if (tid == 0) {
            float gold = v + start_s[tg[0]] + end_s[tg[L - 1]];
            g_loss[b] = shn[0] - gold;
        }
    }
}

// ---------------- kernel: final mean ---------------------------------------
__global__ void k_final(float* __restrict__ out)
{
    __shared__ float s[64];
    int tid = threadIdx.x;
    s[tid] = g_loss[tid];
    __syncthreads();
    if (tid < 32) {
        float v = s[tid] + s[tid + 32];
        #pragma unroll
        for (int o = 16; o; o >>= 1) v += __shfl_xor_sync(0xFFFFFFFFu, v, o);
        if (tid == 0) out[0] = v / 64.f;
    }
}

// ---------------------------------------------------------------------------
extern "C" void kernel_launch(void* const* d_in, const int* in_sizes, int n_in,
                              void* d_out, int out_size)
{
    const int*   words  = (const int*)  d_in[0];
    const int*   target = (const int*)  d_in[1];
    const int*   seqlen = (const int*)  d_in[2];
    const float* emb    = (const float*)d_in[3];
    const float* Wihf   = (const float*)d_in[4];
    const float* Whhf   = (const float*)d_in[5];
    const float* bf     = (const float*)d_in[6];
    const float* Wihb   = (const float*)d_in[7];
    const float* Whhb   = (const float*)d_in[8];
    const float* bb     = (const float*)d_in[9];
    const float* fcW    = (const float*)d_in[10];
    const float* fcb    = (const float*)d_in[11];
    const float* trans  = (const float*)d_in[12];
    const float* starts = (const float*)d_in[13];
    const float* ends   = (const float*)d_in[14];
    float* out = (float*)d_out;

    cudaFuncSetAttribute(k_xg,    cudaFuncAttributeMaxDynamicSharedMemorySize, 131072);
    cudaFuncSetAttribute(k_lstm,  cudaFuncAttributeMaxDynamicSharedMemorySize, 172032);
    cudaFuncSetAttribute(k_feats, cudaFuncAttributeMaxDynamicSharedMemorySize, 104768);

    k_init<<<64, 256>>>();
    dim3 gx(256, 8, 2);
    k_xg<<<gx, 256, 131072>>>(words, seqlen, emb, Wihf, bf, Wihb, bb);
    k_lstm<<<128, 256, 172032>>>(seqlen, Whhf, Whhb);
    k_feats<<<1024, 256, 104768>>>(fcW, fcb);
    k_crf<<<64, 64>>>(target, seqlen, trans, starts, ends);
    k_final<<<1, 64>>>(out);
}